// round 11
// baseline (speedup 1.0000x reference)
#include <cuda_runtime.h>
#include <cuda_bf16.h>
#include <cstdint>

#define V      50000
#define D      128
#define EF     16
#define E_TOT  800000
#define TILE   128
#define NTILES (E_TOT / TILE)
#define LN_EPS 1e-5f
#define NB1    196            // ceil(V/256)

#define LDW2 68   // sW2T stride (u32)
#define LDW1 10   // sW1e stride (u32)
#define LDP  68   // sPb stride (u32)

// smem u32 word offsets (total 28168 w = 112672 B)
#define OW2   0
#define OW1E  (OW2 + 128 * LDW2)            // 8704
#define OPB0  (OW1E + 128 * LDW1)           // 9984
#define OPB1  (OPB0 + 128 * LDP)            // 18688
#define OB2   (OPB1 + 128 * LDP)            // 27392
#define ODST0 (OB2 + 128)                   // 27520
#define ODST1 (ODST0 + 128)                 // 27648
#define OSRC  (ODST1 + 128)                 // 27776
#define OEID  (OSRC + 128)                  // 27904
#define OMASK (OEID + 128)                  // 28032 (4 masks + nseg + pad)
#define OSEG  (OMASK + 8)                   // 28040 (128 seg starts)
#define MSG_SMEM_W (OSEG + 128)             // 28168
#define MSG_SMEM_BYTES (MSG_SMEM_W * 4)

// ---------------- device scratch ----------------
__device__ float    g_agg[(size_t)V * D];
__device__ uint32_t g_Pb[(size_t)V * 64];    // P in bf16x2
__device__ int      g_cnt[V];
__device__ int      g_off[V];
__device__ int      g_woff[V];
__device__ int      g_bsum[256];
__device__ int2     g_pse[E_TOT];            // (src, eid) sorted by dst
__device__ int      g_pdst_s[E_TOT];
__device__ int      g_idx64;

// ---------------- helpers ----------------
__device__ __forceinline__ uint32_t bf2(float lo, float hi) {
    uint32_t r;
    asm("cvt.rn.bf16x2.f32 %0, %1, %2;" : "=r"(r) : "f"(hi), "f"(lo));
    return r;
}
__device__ __forceinline__ float2 unbf2(uint32_t w) {
    __nv_bfloat162 b = *reinterpret_cast<__nv_bfloat162*>(&w);
    return make_float2(__bfloat162float(b.x), __bfloat162float(b.y));
}
__device__ __forceinline__ uint32_t smem_u32(const void* p) {
    uint32_t a;
    asm("{ .reg .u64 t; cvta.to.shared.u64 t, %1; cvt.u32.u64 %0, t; }" : "=r"(a) : "l"(p));
    return a;
}
#define CP_ASYNC16(dst, src) \
    asm volatile("cp.async.cg.shared.global [%0], [%1], 16;" :: "r"(dst), "l"(src))
#define CP_COMMIT() asm volatile("cp.async.commit_group;" ::: "memory")
#define CP_WAIT0()  asm volatile("cp.async.wait_group 0;" ::: "memory")

#define MMA_BF16(d, a0, a1, a2, a3, b0, b1)                                   \
    asm volatile(                                                             \
        "mma.sync.aligned.m16n8k16.row.col.f32.bf16.bf16.f32 "                \
        "{%0,%1,%2,%3}, {%4,%5,%6,%7}, {%8,%9}, {%0,%1,%2,%3};"               \
        : "+f"(d[0]), "+f"(d[1]), "+f"(d[2]), "+f"(d[3])                      \
        : "r"(a0), "r"(a1), "r"(a2), "r"(a3), "r"(b0), "r"(b1))

__device__ __forceinline__ int load_idx(const void* p, int i, int idx64) {
    return idx64 ? (int)reinterpret_cast<const long long*>(p)[i]
                 : reinterpret_cast<const int*>(p)[i];
}

// ---------------- detect dtype + zero g_cnt ----------------
__global__ void detect_zero_kernel(const int* __restrict__ e) {
    int i = blockIdx.x * blockDim.x + threadIdx.x;
    if (i < V / 4) reinterpret_cast<int4*>(g_cnt)[i] = make_int4(0, 0, 0, 0);
    if (i == 0) {
        int nz = 0;
        #pragma unroll
        for (int k = 0; k < 32; k++) nz += (e[2 * k + 1] != 0);
        g_idx64 = (nz == 0) ? 1 : 0;
    }
}

// ---------------- histogram by dst + zero g_agg ----------------
__global__ void hist_zero_kernel(const void* __restrict__ eidx) {
    int i = blockIdx.x * blockDim.x + threadIdx.x;
    if (i < E_TOT) atomicAdd(&g_cnt[load_idx(eidx, E_TOT + i, g_idx64)], 1);
    if (i < (V * D) / 4)
        reinterpret_cast<float4*>(g_agg)[i] = make_float4(0.f, 0.f, 0.f, 0.f);
}

// ---------------- scan: per-block exclusive + block sums ----------------
__global__ void scan1_kernel() {
    __shared__ int s[256];
    int t = threadIdx.x, b = blockIdx.x, i = b * 256 + t;
    int x = (i < V) ? g_cnt[i] : 0;
    s[t] = x; __syncthreads();
    for (int off = 1; off < 256; off <<= 1) {
        int v = (t >= off) ? s[t - off] : 0;
        __syncthreads(); s[t] += v; __syncthreads();
    }
    if (i < V) g_off[i] = s[t] - x;
    if (t == 255) g_bsum[b] = s[t];
}
// ---------------- scan fixup: each block sums bsum[0..b-1] itself ----------------
__global__ void scan3_kernel() {
    __shared__ int red[8];
    int t = threadIdx.x, bb = blockIdx.x;
    int v = (t < bb) ? g_bsum[t] : 0;
    #pragma unroll
    for (int o = 16; o; o >>= 1) v += __shfl_xor_sync(0xffffffffu, v, o);
    if ((t & 31) == 0) red[t >> 5] = v;
    __syncthreads();
    int total = red[0] + red[1] + red[2] + red[3] + red[4] + red[5] + red[6] + red[7];
    int i = bb * 256 + t;
    if (i < V) g_woff[i] = g_off[i] + total;
}

// ---------------- permute edges into dst-sorted order ----------------
__global__ void permute_kernel(const void* __restrict__ eidx) {
    int e = blockIdx.x * blockDim.x + threadIdx.x;
    if (e >= E_TOT) return;
    int idx64 = g_idx64;
    int s = load_idx(eidx, e, idx64);
    int d = load_idx(eidx, E_TOT + e, idx64);
    int pos = atomicAdd(&g_woff[d], 1);
    g_pse[pos] = make_int2(s, e);
    g_pdst_s[pos] = d;
}

// ---------------- P = bf16(h @ W1h + b1) per node ----------------
#define P_SMEM_W (2 * 128 * 68 + 128)
__global__ void __launch_bounds__(256)
p_kernel(const float* __restrict__ h, const float* __restrict__ W1,
         const float* __restrict__ b1) {
    extern __shared__ uint32_t sm[];
    uint32_t* sH = sm;                 // [128][68] bf16x2
    uint32_t* sW = sH + 128 * 68;      // [n][68]
    float*    sB = reinterpret_cast<float*>(sW + 128 * 68);

    const int tid = threadIdx.x, lane = tid & 31, warp = tid >> 5;
    const int gid = lane >> 2, tig = lane & 3, rw = warp * 16;
    const int row0 = blockIdx.x * 128;
    const int valid = (V - row0 < 128) ? (V - row0) : 128;

    __nv_bfloat16* sWb = reinterpret_cast<__nv_bfloat16*>(sW);
    for (int i = tid; i < 128 * 128; i += 256) {
        int k = i >> 7, n = i & 127;
        sWb[(n * 68 + (k >> 1)) * 2 + (k & 1)] = __float2bfloat16(W1[i]);
    }
    if (tid < 128) sB[tid] = b1[tid];

    #pragma unroll
    for (int j = 0; j < 16; j++) {
        int idx = tid + j * 256;
        int row = idx >> 5, slot = idx & 31;
        float4 v = {0.f, 0.f, 0.f, 0.f};
        if (row < valid)
            v = reinterpret_cast<const float4*>(h)[(size_t)(row0 + row) * 32 + slot];
        sH[row * 68 + slot * 2]     = bf2(v.x, v.y);
        sH[row * 68 + slot * 2 + 1] = bf2(v.z, v.w);
    }
    __syncthreads();

    float acc[16][4];
    #pragma unroll
    for (int nt = 0; nt < 16; nt++)
        #pragma unroll
        for (int q = 0; q < 4; q++) acc[nt][q] = 0.f;

    const uint32_t* Xr = sH + (rw + gid) * 68 + tig;
    const uint32_t* Bp = sW + gid * 68 + tig;
    for (int ks = 0; ks < 8; ks++) {
        uint32_t a0 = Xr[ks * 8];
        uint32_t a1 = Xr[ks * 8 + 8 * 68];
        uint32_t a2 = Xr[ks * 8 + 4];
        uint32_t a3 = Xr[ks * 8 + 8 * 68 + 4];
        #pragma unroll
        for (int nt = 0; nt < 16; nt++) {
            uint32_t b0 = Bp[nt * 8 * 68 + ks * 8];
            uint32_t b1r = Bp[nt * 8 * 68 + ks * 8 + 4];
            MMA_BF16(acc[nt], a0, a1, a2, a3, b0, b1r);
        }
    }

    int r0 = rw + gid, r1 = rw + gid + 8;
    #pragma unroll
    for (int nt = 0; nt < 16; nt++) {
        int col = nt * 8 + 2 * tig;
        float bb0 = sB[col], bb1 = sB[col + 1];
        if (r0 < valid)
            g_Pb[(size_t)(row0 + r0) * 64 + nt * 4 + tig] =
                bf2(acc[nt][0] + bb0, acc[nt][1] + bb1);
        if (r1 < valid)
            g_Pb[(size_t)(row0 + r1) * 64 + nt * 4 + tig] =
                bf2(acc[nt][2] + bb0, acc[nt][3] + bb1);
    }
}

// ---------------- message kernel (persistent, pipelined) ----------------
__global__ void __launch_bounds__(256, 2)
msg_kernel(const float* __restrict__ ea,
           const float* __restrict__ W1,
           const float* __restrict__ W2,
           const float* __restrict__ b2) {
    extern __shared__ uint32_t sm[];
    uint32_t* sW2T = sm + OW2;
    uint32_t* sW1e = sm + OW1E;
    uint32_t* sPb[2] = { sm + OPB0, sm + OPB1 };
    float*    sB2  = reinterpret_cast<float*>(sm + OB2);
    int*      sDstB[2] = { reinterpret_cast<int*>(sm + ODST0),
                           reinterpret_cast<int*>(sm + ODST1) };
    int*      sSrc = reinterpret_cast<int*>(sm + OSRC);
    int*      sEid = reinterpret_cast<int*>(sm + OEID);
    int*      sMask = reinterpret_cast<int*>(sm + OMASK);      // [4] + nseg at [4]
    int*      sSeg  = reinterpret_cast<int*>(sm + OSEG);       // [128]
    const uint32_t sbase = smem_u32(sm);

    const int tid = threadIdx.x, lane = tid & 31, warp = tid >> 5;
    const int gid = lane >> 2, tig = lane & 3, rw = warp * 16;
    const int r0 = rw + gid, r1 = rw + gid + 8;

    // ---- weights once ----
    __nv_bfloat16* w1b = reinterpret_cast<__nv_bfloat16*>(sW1e);
    for (int i = tid; i < 16 * 128; i += 256) {
        int k = i >> 7, n = i & 127;
        w1b[(n * LDW1 + (k >> 1)) * 2 + (k & 1)] = __float2bfloat16(W1[(128 + k) * 128 + n]);
    }
    __nv_bfloat16* w2b = reinterpret_cast<__nv_bfloat16*>(sW2T);
    for (int i = tid; i < 128 * 128; i += 256) {
        int k = i >> 7, n = i & 127;
        w2b[(n * LDW2 + (k >> 1)) * 2 + (k & 1)] = __float2bfloat16(W2[i]);
    }
    if (tid < 128) sB2[tid] = b2[tid];

    const int stride = gridDim.x;
    const int t0 = blockIdx.x;

    // ---- prologue: indices + prefetch for first tile ----
    if (t0 < NTILES && tid < TILE) {
        int2 v = g_pse[t0 * TILE + tid];
        sSrc[tid] = v.x; sEid[tid] = v.y;
        sDstB[0][tid] = g_pdst_s[t0 * TILE + tid];
    }
    __syncthreads();   // also covers weight preload

    uint32_t eaU[4];
    if (t0 < NTILES) {
        #pragma unroll
        for (int j = 0; j < 8; j++) {
            int c = tid + j * 256;
            int row = c >> 4, q = c & 15;
            uint32_t dst = sbase + OPB0 * 4 + row * (LDP * 4) + q * 16;
            const char* src = reinterpret_cast<const char*>(g_Pb)
                              + ((size_t)sSrc[row] * 256 + q * 16);
            CP_ASYNC16(dst, src);
        }
        const float2* p0 = reinterpret_cast<const float2*>(ea + (size_t)sEid[r0] * 16);
        const float2* p1 = reinterpret_cast<const float2*>(ea + (size_t)sEid[r1] * 16);
        float2 x0 = p0[tig], x2 = p0[tig + 4];
        float2 x1 = p1[tig], x3 = p1[tig + 4];
        eaU[0] = bf2(x0.x, x0.y); eaU[2] = bf2(x2.x, x2.y);
        eaU[1] = bf2(x1.x, x1.y); eaU[3] = bf2(x3.x, x3.y);
    }
    CP_COMMIT();

    int it = 0;
    for (int t = t0; t < NTILES; t += stride, it++) {
        const int b = it & 1, nb = b ^ 1;
        const int tn = t + stride;
        int* sDstCur = sDstB[b];

        CP_WAIT0();
        if (tn < NTILES && tid < TILE) {
            int2 v = g_pse[tn * TILE + tid];
            sSrc[tid] = v.x; sEid[tid] = v.y;
            sDstB[nb][tid] = g_pdst_s[tn * TILE + tid];
        }
        __syncthreads();   // P(t) consumable + idx(tn) visible

        // ---- segment metadata for current tile ----
        int flag = 0;
        if (tid < TILE)
            flag = (tid == 0) || (sDstCur[tid] != sDstCur[tid - 1]);
        unsigned msk = __ballot_sync(0xffffffffu, flag);
        if (tid < TILE && lane == 0) sMask[warp] = (int)msk;
        __syncthreads();
        if (tid < TILE) {
            if (flag) {
                int rank = __popc((unsigned)sMask[warp] & ((1u << lane) - 1));
                #pragma unroll
                for (int w = 0; w < 3; w++)
                    if (w < warp) rank += __popc((unsigned)sMask[w]);
                sSeg[rank] = tid;
            }
            if (tid == 0)
                sMask[4] = __popc((unsigned)sMask[0]) + __popc((unsigned)sMask[1])
                         + __popc((unsigned)sMask[2]) + __popc((unsigned)sMask[3]);
        }

        uint32_t a0 = eaU[0], a1 = eaU[1], a2 = eaU[2], a3 = eaU[3];

        // prefetch next tile
        if (tn < NTILES) {
            uint32_t dbase = sbase + (nb ? OPB1 : OPB0) * 4;
            #pragma unroll
            for (int j = 0; j < 8; j++) {
                int c = tid + j * 256;
                int row = c >> 4, q = c & 15;
                const char* src = reinterpret_cast<const char*>(g_Pb)
                                  + ((size_t)sSrc[row] * 256 + q * 16);
                CP_ASYNC16(dbase + row * (LDP * 4) + q * 16, src);
            }
            const float2* p0 = reinterpret_cast<const float2*>(ea + (size_t)sEid[r0] * 16);
            const float2* p1 = reinterpret_cast<const float2*>(ea + (size_t)sEid[r1] * 16);
            float2 x0 = p0[tig], x2 = p0[tig + 4];
            float2 x1 = p1[tig], x3 = p1[tig + 4];
            eaU[0] = bf2(x0.x, x0.y); eaU[2] = bf2(x2.x, x2.y);
            eaU[1] = bf2(x1.x, x1.y); eaU[3] = bf2(x3.x, x3.y);
        }
        CP_COMMIT();

        // ---- G1: acc = P[src] += ea @ W1e ----
        float acc[16][4];
        {
            const uint32_t* Pr0 = sPb[b] + r0 * LDP + tig;
            const uint32_t* Pr1 = sPb[b] + r1 * LDP + tig;
            #pragma unroll
            for (int nt = 0; nt < 16; nt++) {
                float2 lo = unbf2(Pr0[nt * 4]);
                float2 hi = unbf2(Pr1[nt * 4]);
                acc[nt][0] = lo.x; acc[nt][1] = lo.y;
                acc[nt][2] = hi.x; acc[nt][3] = hi.y;
            }
            const uint32_t* Bp = sW1e + gid * LDW1 + tig;
            #pragma unroll
            for (int nt = 0; nt < 16; nt++) {
                uint32_t b0 = Bp[nt * 8 * LDW1];
                uint32_t b1r = Bp[nt * 8 * LDW1 + 4];
                MMA_BF16(acc[nt], a0, a1, a2, a3, b0, b1r);
            }
        }

        // ---- EPI1: hidden = bf16(relu(acc)) ----
        uint32_t hid_lo[16], hid_hi[16];
        #pragma unroll
        for (int nt = 0; nt < 16; nt++) {
            hid_lo[nt] = bf2(fmaxf(acc[nt][0], 0.f), fmaxf(acc[nt][1], 0.f));
            hid_hi[nt] = bf2(fmaxf(acc[nt][2], 0.f), fmaxf(acc[nt][3], 0.f));
        }

        // ---- G2: D2 = hidden @ W2 ----
        #pragma unroll
        for (int nt = 0; nt < 16; nt++)
            #pragma unroll
            for (int q = 0; q < 4; q++) acc[nt][q] = 0.f;
        {
            const uint32_t* Bp = sW2T + gid * LDW2 + tig;
            for (int ks = 0; ks < 8; ks++) {
                uint32_t c0 = hid_lo[2 * ks];
                uint32_t c1 = hid_hi[2 * ks];
                uint32_t c2 = hid_lo[2 * ks + 1];
                uint32_t c3 = hid_hi[2 * ks + 1];
                #pragma unroll
                for (int nt = 0; nt < 16; nt++) {
                    uint32_t b0 = Bp[nt * 8 * LDW2 + ks * 8];
                    uint32_t b1r = Bp[nt * 8 * LDW2 + ks * 8 + 4];
                    MMA_BF16(acc[nt], c0, c1, c2, c3, b0, b1r);
                }
            }
        }

        // ---- EPI2 + segment-list reduce (sD2 aliases sPb[b]) ----
        float* sD2 = reinterpret_cast<float*>(sPb[b]);
        #pragma unroll
        for (int h = 0; h < 2; h++) {
            #pragma unroll
            for (int nt = 0; nt < 8; nt++) {
                int gnt = h * 8 + nt;
                int lcol = nt * 8 + 2 * tig;
                int gcol = h * 64 + lcol;
                float bb0 = sB2[gcol], bb1 = sB2[gcol + 1];
                *reinterpret_cast<float2*>(sD2 + r0 * LDP + lcol) =
                    make_float2(acc[gnt][0] + bb0, acc[gnt][1] + bb1);
                *reinterpret_cast<float2*>(sD2 + r1 * LDP + lcol) =
                    make_float2(acc[gnt][2] + bb0, acc[gnt][3] + bb1);
            }
            __syncthreads();
            {
                const int nseg = sMask[4];
                // warp w handles segments w, w+8, ...; lane owns cols 2*lane, 2*lane+1
                for (int s = warp; s < nseg; s += 8) {
                    int a = sSeg[s];
                    int bend = (s + 1 < nseg) ? sSeg[s + 1] : TILE;
                    int dstv = sDstCur[a];
                    float s0 = 0.f, s1 = 0.f;
                    for (int r = a; r < bend; r++) {
                        float2 v = *reinterpret_cast<const float2*>(sD2 + r * LDP + 2 * lane);
                        s0 += v.x; s1 += v.y;
                    }
                    asm volatile("red.global.add.v2.f32 [%0], {%1,%2};"
                                 :: "l"(g_agg + (size_t)dstv * 128 + h * 64 + 2 * lane),
                                    "f"(s0), "f"(s1) : "memory");
                }
            }
            __syncthreads();
        }
    }
}

// ---------------- residual + LayerNorm ----------------
__global__ void ln_kernel(const float* __restrict__ h,
                          const float* __restrict__ gamma,
                          const float* __restrict__ beta,
                          float* __restrict__ out) {
    int gw = (blockIdx.x * blockDim.x + threadIdx.x) >> 5;
    int l  = threadIdx.x & 31;
    if (gw >= V) return;

    float4 hv = reinterpret_cast<const float4*>(h)[(size_t)gw * 32 + l];
    float4 av = reinterpret_cast<const float4*>(g_agg)[(size_t)gw * 32 + l];
    float inv = 1.0f / (1.0f + (float)g_cnt[gw]);

    float4 y;
    y.x = hv.x + av.x * inv; y.y = hv.y + av.y * inv;
    y.z = hv.z + av.z * inv; y.w = hv.w + av.w * inv;

    float s = y.x + y.y + y.z + y.w;
    #pragma unroll
    for (int o = 16; o; o >>= 1) s += __shfl_xor_sync(0xffffffffu, s, o);
    float mu = s * (1.0f / 128.0f);

    float dx = y.x - mu, dy = y.y - mu, dz = y.z - mu, dw = y.w - mu;
    float q = dx * dx + dy * dy + dz * dz + dw * dw;
    #pragma unroll
    for (int o = 16; o; o >>= 1) q += __shfl_xor_sync(0xffffffffu, q, o);
    float rstd = rsqrtf(q * (1.0f / 128.0f) + LN_EPS);

    float4 g4 = reinterpret_cast<const float4*>(gamma)[l];
    float4 b4 = reinterpret_cast<const float4*>(beta)[l];
    float4 o4;
    o4.x = dx * rstd * g4.x + b4.x; o4.y = dy * rstd * g4.y + b4.y;
    o4.z = dz * rstd * g4.z + b4.z; o4.w = dw * rstd * g4.w + b4.w;
    reinterpret_cast<float4*>(out)[(size_t)gw * 32 + l] = o4;
}

// ---------------- launcher ----------------
extern "C" void kernel_launch(void* const* d_in, const int* in_sizes, int n_in,
                              void* d_out, int out_size) {
    const float* h     = (const float*)d_in[0];
    const void*  eidx  = d_in[1];
    const float* ea    = (const float*)d_in[2];
    const float* W1    = (const float*)d_in[3];
    const float* b1    = (const float*)d_in[4];
    const float* W2    = (const float*)d_in[5];
    const float* b2    = (const float*)d_in[6];
    const float* gamma = (const float*)d_in[7];
    const float* beta  = (const float*)d_in[8];
    float*       out   = (float*)d_out;

    cudaFuncSetAttribute(msg_kernel, cudaFuncAttributeMaxDynamicSharedMemorySize,
                         MSG_SMEM_BYTES);
    cudaFuncSetAttribute(p_kernel, cudaFuncAttributeMaxDynamicSharedMemorySize,
                         P_SMEM_W * 4);

    int sms = 148;
    if (cudaDeviceGetAttribute(&sms, cudaDevAttrMultiProcessorCount, 0) != cudaSuccess
        || sms <= 0) sms = 148;

    detect_zero_kernel<<<(V / 4 + 255) / 256, 256>>>((const int*)eidx);
    hist_zero_kernel<<<(V * D / 4 + 255) / 256, 256>>>(eidx);
    scan1_kernel<<<NB1, 256>>>();
    scan3_kernel<<<NB1, 256>>>();
    permute_kernel<<<(E_TOT + 255) / 256, 256>>>(eidx);
    p_kernel<<<(V + 127) / 128, 256, P_SMEM_W * 4>>>(h, W1, b1);
    msg_kernel<<<2 * sms, 256, MSG_SMEM_BYTES>>>(ea, W1, W2, b2);
    ln_kernel<<<(V * 32 + 255) / 256, 256>>>(h, gamma, beta, out);
}

// round 12
// speedup vs baseline: 1.2716x; 1.2716x over previous
#include <cuda_runtime.h>
#include <cuda_bf16.h>
#include <cstdint>

#define V      50000
#define D      128
#define EF     16
#define E_TOT  800000
#define TILE   128
#define NTILES (E_TOT / TILE)
#define LN_EPS 1e-5f
#define NB1    196            // ceil(V/256)

#define LDW2 68   // sW2T stride (u32)
#define LDW1 10   // sW1e stride (u32)
#define LDP  68   // sPb stride (u32)

// smem u32 word offsets (total 28032 w = 112128 B)
#define OW2   0
#define OW1E  (OW2 + 128 * LDW2)            // 8704
#define OPB0  (OW1E + 128 * LDW1)           // 9984
#define OPB1  (OPB0 + 128 * LDP)            // 18688
#define OB2   (OPB1 + 128 * LDP)            // 27392
#define ODST0 (OB2 + 128)                   // 27520
#define ODST1 (ODST0 + 128)                 // 27648
#define OSRC  (ODST1 + 128)                 // 27776
#define OEID  (OSRC + 128)                  // 27904
#define MSG_SMEM_W (OEID + 128)             // 28032
#define MSG_SMEM_BYTES (MSG_SMEM_W * 4)

// ---------------- device scratch ----------------
__device__ float    g_agg[(size_t)V * D];
__device__ uint32_t g_Pb[(size_t)V * 64];    // P in bf16x2, 12.8 MB
__device__ int      g_cnt[V];
__device__ int      g_off[V];
__device__ int      g_woff[V];
__device__ int      g_bsum[256];
__device__ int2     g_pse[E_TOT];            // (src, eid) sorted by dst
__device__ int      g_pdst_s[E_TOT];
__device__ int      g_idx64;

// ---------------- helpers ----------------
__device__ __forceinline__ uint32_t bf2(float lo, float hi) {
    uint32_t r;
    asm("cvt.rn.bf16x2.f32 %0, %1, %2;" : "=r"(r) : "f"(hi), "f"(lo));
    return r;
}
__device__ __forceinline__ float2 unbf2(uint32_t w) {
    __nv_bfloat162 b = *reinterpret_cast<__nv_bfloat162*>(&w);
    return make_float2(__bfloat162float(b.x), __bfloat162float(b.y));
}
__device__ __forceinline__ uint32_t smem_u32(const void* p) {
    uint32_t a;
    asm("{ .reg .u64 t; cvta.to.shared.u64 t, %1; cvt.u32.u64 %0, t; }" : "=r"(a) : "l"(p));
    return a;
}
#define CP_ASYNC16(dst, src) \
    asm volatile("cp.async.cg.shared.global [%0], [%1], 16;" :: "r"(dst), "l"(src))
#define CP_COMMIT() asm volatile("cp.async.commit_group;" ::: "memory")
#define CP_WAIT0()  asm volatile("cp.async.wait_group 0;" ::: "memory")

#define MMA_BF16(d, a0, a1, a2, a3, b0, b1)                                   \
    asm volatile(                                                             \
        "mma.sync.aligned.m16n8k16.row.col.f32.bf16.bf16.f32 "                \
        "{%0,%1,%2,%3}, {%4,%5,%6,%7}, {%8,%9}, {%0,%1,%2,%3};"               \
        : "+f"(d[0]), "+f"(d[1]), "+f"(d[2]), "+f"(d[3])                      \
        : "r"(a0), "r"(a1), "r"(a2), "r"(a3), "r"(b0), "r"(b1))

__device__ __forceinline__ int load_idx(const void* p, int i, int idx64) {
    return idx64 ? (int)reinterpret_cast<const long long*>(p)[i]
                 : reinterpret_cast<const int*>(p)[i];
}

// ---------------- detect dtype + zero g_cnt ----------------
__global__ void detect_zero_kernel(const int* __restrict__ e) {
    int i = blockIdx.x * blockDim.x + threadIdx.x;
    if (i < V / 4) reinterpret_cast<int4*>(g_cnt)[i] = make_int4(0, 0, 0, 0);
    if (i == 0) {
        int nz = 0;
        #pragma unroll
        for (int k = 0; k < 32; k++) nz += (e[2 * k + 1] != 0);
        g_idx64 = (nz == 0) ? 1 : 0;
    }
}

// ---------------- histogram by dst + zero g_agg ----------------
__global__ void hist_zero_kernel(const void* __restrict__ eidx) {
    int i = blockIdx.x * blockDim.x + threadIdx.x;
    if (i < E_TOT) atomicAdd(&g_cnt[load_idx(eidx, E_TOT + i, g_idx64)], 1);
    if (i < (V * D) / 4)
        reinterpret_cast<float4*>(g_agg)[i] = make_float4(0.f, 0.f, 0.f, 0.f);
}

// ---------------- scan: per-block exclusive + block sums ----------------
__global__ void scan1_kernel() {
    __shared__ int s[256];
    int t = threadIdx.x, b = blockIdx.x, i = b * 256 + t;
    int x = (i < V) ? g_cnt[i] : 0;
    s[t] = x; __syncthreads();
    for (int off = 1; off < 256; off <<= 1) {
        int v = (t >= off) ? s[t - off] : 0;
        __syncthreads(); s[t] += v; __syncthreads();
    }
    if (i < V) g_off[i] = s[t] - x;
    if (t == 255) g_bsum[b] = s[t];
}
// ---------------- scan fixup: each block sums bsum[0..b-1] itself ----------------
__global__ void scan3_kernel() {
    __shared__ int red[8];
    int t = threadIdx.x, bb = blockIdx.x;
    int v = (t < bb) ? g_bsum[t] : 0;
    #pragma unroll
    for (int o = 16; o; o >>= 1) v += __shfl_xor_sync(0xffffffffu, v, o);
    if ((t & 31) == 0) red[t >> 5] = v;
    __syncthreads();
    int total = red[0] + red[1] + red[2] + red[3] + red[4] + red[5] + red[6] + red[7];
    int i = bb * 256 + t;
    if (i < V) g_woff[i] = g_off[i] + total;
}

// ---------------- permute edges into dst-sorted order ----------------
__global__ void permute_kernel(const void* __restrict__ eidx) {
    int e = blockIdx.x * blockDim.x + threadIdx.x;
    if (e >= E_TOT) return;
    int idx64 = g_idx64;
    int s = load_idx(eidx, e, idx64);
    int d = load_idx(eidx, E_TOT + e, idx64);
    int pos = atomicAdd(&g_woff[d], 1);
    g_pse[pos] = make_int2(s, e);
    g_pdst_s[pos] = d;
}

// ---------------- P = bf16(h @ W1h + b1) per node ----------------
#define P_SMEM_W (2 * 128 * 68 + 128)
__global__ void __launch_bounds__(256)
p_kernel(const float* __restrict__ h, const float* __restrict__ W1,
         const float* __restrict__ b1) {
    extern __shared__ uint32_t sm[];
    uint32_t* sH = sm;                 // [128][68] bf16x2
    uint32_t* sW = sH + 128 * 68;      // [n][68]
    float*    sB = reinterpret_cast<float*>(sW + 128 * 68);

    const int tid = threadIdx.x, lane = tid & 31, warp = tid >> 5;
    const int gid = lane >> 2, tig = lane & 3, rw = warp * 16;
    const int row0 = blockIdx.x * 128;
    const int valid = (V - row0 < 128) ? (V - row0) : 128;

    __nv_bfloat16* sWb = reinterpret_cast<__nv_bfloat16*>(sW);
    for (int i = tid; i < 128 * 128; i += 256) {
        int k = i >> 7, n = i & 127;
        sWb[(n * 68 + (k >> 1)) * 2 + (k & 1)] = __float2bfloat16(W1[i]);
    }
    if (tid < 128) sB[tid] = b1[tid];

    #pragma unroll
    for (int j = 0; j < 16; j++) {
        int idx = tid + j * 256;
        int row = idx >> 5, slot = idx & 31;
        float4 v = {0.f, 0.f, 0.f, 0.f};
        if (row < valid)
            v = reinterpret_cast<const float4*>(h)[(size_t)(row0 + row) * 32 + slot];
        sH[row * 68 + slot * 2]     = bf2(v.x, v.y);
        sH[row * 68 + slot * 2 + 1] = bf2(v.z, v.w);
    }
    __syncthreads();

    float acc[16][4];
    #pragma unroll
    for (int nt = 0; nt < 16; nt++)
        #pragma unroll
        for (int q = 0; q < 4; q++) acc[nt][q] = 0.f;

    const uint32_t* Xr = sH + (rw + gid) * 68 + tig;
    const uint32_t* Bp = sW + gid * 68 + tig;
    for (int ks = 0; ks < 8; ks++) {
        uint32_t a0 = Xr[ks * 8];
        uint32_t a1 = Xr[ks * 8 + 8 * 68];
        uint32_t a2 = Xr[ks * 8 + 4];
        uint32_t a3 = Xr[ks * 8 + 8 * 68 + 4];
        #pragma unroll
        for (int nt = 0; nt < 16; nt++) {
            uint32_t b0 = Bp[nt * 8 * 68 + ks * 8];
            uint32_t b1r = Bp[nt * 8 * 68 + ks * 8 + 4];
            MMA_BF16(acc[nt], a0, a1, a2, a3, b0, b1r);
        }
    }

    int r0 = rw + gid, r1 = rw + gid + 8;
    #pragma unroll
    for (int nt = 0; nt < 16; nt++) {
        int col = nt * 8 + 2 * tig;
        float bb0 = sB[col], bb1 = sB[col + 1];
        if (r0 < valid)
            g_Pb[(size_t)(row0 + r0) * 64 + nt * 4 + tig] =
                bf2(acc[nt][0] + bb0, acc[nt][1] + bb1);
        if (r1 < valid)
            g_Pb[(size_t)(row0 + r1) * 64 + nt * 4 + tig] =
                bf2(acc[nt][2] + bb0, acc[nt][3] + bb1);
    }
}

// ---------------- message kernel (persistent, pipelined) ----------------
__global__ void __launch_bounds__(256, 2)
msg_kernel(const float* __restrict__ ea,
           const float* __restrict__ W1,
           const float* __restrict__ W2,
           const float* __restrict__ b2) {
    extern __shared__ uint32_t sm[];
    uint32_t* sW2T = sm + OW2;
    uint32_t* sW1e = sm + OW1E;
    uint32_t* sPb[2] = { sm + OPB0, sm + OPB1 };
    float*    sB2  = reinterpret_cast<float*>(sm + OB2);
    int*      sDstB[2] = { reinterpret_cast<int*>(sm + ODST0),
                           reinterpret_cast<int*>(sm + ODST1) };
    int*      sSrc = reinterpret_cast<int*>(sm + OSRC);
    int*      sEid = reinterpret_cast<int*>(sm + OEID);
    const uint32_t sbase = smem_u32(sm);

    const int tid = threadIdx.x, lane = tid & 31, warp = tid >> 5;
    const int gid = lane >> 2, tig = lane & 3, rw = warp * 16;
    const int r0 = rw + gid, r1 = rw + gid + 8;

    // ---- weights once ----
    __nv_bfloat16* w1b = reinterpret_cast<__nv_bfloat16*>(sW1e);
    for (int i = tid; i < 16 * 128; i += 256) {
        int k = i >> 7, n = i & 127;
        w1b[(n * LDW1 + (k >> 1)) * 2 + (k & 1)] = __float2bfloat16(W1[(128 + k) * 128 + n]);
    }
    __nv_bfloat16* w2b = reinterpret_cast<__nv_bfloat16*>(sW2T);
    for (int i = tid; i < 128 * 128; i += 256) {
        int k = i >> 7, n = i & 127;
        w2b[(n * LDW2 + (k >> 1)) * 2 + (k & 1)] = __float2bfloat16(W2[i]);
    }
    if (tid < 128) sB2[tid] = b2[tid];

    const int stride = gridDim.x;
    const int t0 = blockIdx.x;

    // ---- prologue: indices + prefetch for first tile ----
    if (t0 < NTILES && tid < TILE) {
        int2 v = g_pse[t0 * TILE + tid];
        sSrc[tid] = v.x; sEid[tid] = v.y;
        sDstB[0][tid] = g_pdst_s[t0 * TILE + tid];
    }
    __syncthreads();   // also covers weight preload

    uint32_t eaU[4];
    if (t0 < NTILES) {
        #pragma unroll
        for (int j = 0; j < 8; j++) {
            int c = tid + j * 256;
            int row = c >> 4, q = c & 15;
            uint32_t dst = sbase + OPB0 * 4 + row * (LDP * 4) + q * 16;
            const char* src = reinterpret_cast<const char*>(g_Pb)
                              + ((size_t)sSrc[row] * 256 + q * 16);
            CP_ASYNC16(dst, src);
        }
        const float2* p0 = reinterpret_cast<const float2*>(ea + (size_t)sEid[r0] * 16);
        const float2* p1 = reinterpret_cast<const float2*>(ea + (size_t)sEid[r1] * 16);
        float2 x0 = p0[tig], x2 = p0[tig + 4];
        float2 x1 = p1[tig], x3 = p1[tig + 4];
        eaU[0] = bf2(x0.x, x0.y); eaU[2] = bf2(x2.x, x2.y);
        eaU[1] = bf2(x1.x, x1.y); eaU[3] = bf2(x3.x, x3.y);
    }
    CP_COMMIT();

    int it = 0;
    for (int t = t0; t < NTILES; t += stride, it++) {
        const int b = it & 1, nb = b ^ 1;
        const int tn = t + stride;

        CP_WAIT0();
        if (tn < NTILES && tid < TILE) {
            int2 v = g_pse[tn * TILE + tid];
            sSrc[tid] = v.x; sEid[tid] = v.y;
            sDstB[nb][tid] = g_pdst_s[tn * TILE + tid];
        }
        __syncthreads();   // P(t) consumable + idx(tn) visible + prior reduce done

        uint32_t a0 = eaU[0], a1 = eaU[1], a2 = eaU[2], a3 = eaU[3];

        if (tn < NTILES) {
            uint32_t dbase = sbase + (nb ? OPB1 : OPB0) * 4;
            #pragma unroll
            for (int j = 0; j < 8; j++) {
                int c = tid + j * 256;
                int row = c >> 4, q = c & 15;
                const char* src = reinterpret_cast<const char*>(g_Pb)
                                  + ((size_t)sSrc[row] * 256 + q * 16);
                CP_ASYNC16(dbase + row * (LDP * 4) + q * 16, src);
            }
            const float2* p0 = reinterpret_cast<const float2*>(ea + (size_t)sEid[r0] * 16);
            const float2* p1 = reinterpret_cast<const float2*>(ea + (size_t)sEid[r1] * 16);
            float2 x0 = p0[tig], x2 = p0[tig + 4];
            float2 x1 = p1[tig], x3 = p1[tig + 4];
            eaU[0] = bf2(x0.x, x0.y); eaU[2] = bf2(x2.x, x2.y);
            eaU[1] = bf2(x1.x, x1.y); eaU[3] = bf2(x3.x, x3.y);
        }
        CP_COMMIT();

        // ---- G1: acc = P[src] += ea @ W1e ----
        float acc[16][4];
        {
            const uint32_t* Pr0 = sPb[b] + r0 * LDP + tig;
            const uint32_t* Pr1 = sPb[b] + r1 * LDP + tig;
            #pragma unroll
            for (int nt = 0; nt < 16; nt++) {
                float2 lo = unbf2(Pr0[nt * 4]);
                float2 hi = unbf2(Pr1[nt * 4]);
                acc[nt][0] = lo.x; acc[nt][1] = lo.y;
                acc[nt][2] = hi.x; acc[nt][3] = hi.y;
            }
            const uint32_t* Bp = sW1e + gid * LDW1 + tig;
            #pragma unroll
            for (int nt = 0; nt < 16; nt++) {
                uint32_t b0 = Bp[nt * 8 * LDW1];
                uint32_t b1r = Bp[nt * 8 * LDW1 + 4];
                MMA_BF16(acc[nt], a0, a1, a2, a3, b0, b1r);
            }
        }

        // ---- EPI1: hidden = bf16(relu(acc)) ----
        uint32_t hid_lo[16], hid_hi[16];
        #pragma unroll
        for (int nt = 0; nt < 16; nt++) {
            hid_lo[nt] = bf2(fmaxf(acc[nt][0], 0.f), fmaxf(acc[nt][1], 0.f));
            hid_hi[nt] = bf2(fmaxf(acc[nt][2], 0.f), fmaxf(acc[nt][3], 0.f));
        }

        // ---- G2: D2 = hidden @ W2 ----
        #pragma unroll
        for (int nt = 0; nt < 16; nt++)
            #pragma unroll
            for (int q = 0; q < 4; q++) acc[nt][q] = 0.f;
        {
            const uint32_t* Bp = sW2T + gid * LDW2 + tig;
            for (int ks = 0; ks < 8; ks++) {
                uint32_t c0 = hid_lo[2 * ks];
                uint32_t c1 = hid_hi[2 * ks];
                uint32_t c2 = hid_lo[2 * ks + 1];
                uint32_t c3 = hid_hi[2 * ks + 1];
                #pragma unroll
                for (int nt = 0; nt < 16; nt++) {
                    uint32_t b0 = Bp[nt * 8 * LDW2 + ks * 8];
                    uint32_t b1r = Bp[nt * 8 * LDW2 + ks * 8 + 4];
                    MMA_BF16(acc[nt], c0, c1, c2, c3, b0, b1r);
                }
            }
        }

        // ---- EPI2 + segmented reduce (sD2 aliases sPb[b]) ----
        float* sD2 = reinterpret_cast<float*>(sPb[b]);
        int* sDst = sDstB[b];
        #pragma unroll
        for (int h = 0; h < 2; h++) {
            #pragma unroll
            for (int nt = 0; nt < 8; nt++) {
                int gnt = h * 8 + nt;
                int lcol = nt * 8 + 2 * tig;
                int gcol = h * 64 + lcol;
                float bb0 = sB2[gcol], bb1 = sB2[gcol + 1];
                *reinterpret_cast<float2*>(sD2 + r0 * LDP + lcol) =
                    make_float2(acc[gnt][0] + bb0, acc[gnt][1] + bb1);
                *reinterpret_cast<float2*>(sD2 + r1 * LDP + lcol) =
                    make_float2(acc[gnt][2] + bb0, acc[gnt][3] + bb1);
            }
            __syncthreads();
            {
                int colblk = warp & 1;
                int rowq = (warp >> 1) * 32;
                int lcol = colblk * 32 + lane;
                int gcol = h * 64 + lcol;
                float a = 0.f;
                int cur = sDst[rowq];
                #pragma unroll 4
                for (int r = 0; r < 32; r++) {
                    int row = rowq + r;
                    int dr = sDst[row];
                    if (r > 0 && dr != cur) {
                        atomicAdd(&g_agg[(size_t)cur * 128 + gcol], a);
                        a = 0.f; cur = dr;
                    }
                    a += sD2[row * LDP + lcol];
                }
                atomicAdd(&g_agg[(size_t)cur * 128 + gcol], a);
            }
            if (h == 0) __syncthreads();   // h=1's trailing barrier is covered by loop-top barrier
        }
    }
}

// ---------------- residual + LayerNorm ----------------
__global__ void ln_kernel(const float* __restrict__ h,
                          const float* __restrict__ gamma,
                          const float* __restrict__ beta,
                          float* __restrict__ out) {
    int gw = (blockIdx.x * blockDim.x + threadIdx.x) >> 5;
    int l  = threadIdx.x & 31;
    if (gw >= V) return;

    float4 hv = reinterpret_cast<const float4*>(h)[(size_t)gw * 32 + l];
    float4 av = reinterpret_cast<const float4*>(g_agg)[(size_t)gw * 32 + l];
    float inv = 1.0f / (1.0f + (float)g_cnt[gw]);

    float4 y;
    y.x = hv.x + av.x * inv; y.y = hv.y + av.y * inv;
    y.z = hv.z + av.z * inv; y.w = hv.w + av.w * inv;

    float s = y.x + y.y + y.z + y.w;
    #pragma unroll
    for (int o = 16; o; o >>= 1) s += __shfl_xor_sync(0xffffffffu, s, o);
    float mu = s * (1.0f / 128.0f);

    float dx = y.x - mu, dy = y.y - mu, dz = y.z - mu, dw = y.w - mu;
    float q = dx * dx + dy * dy + dz * dz + dw * dw;
    #pragma unroll
    for (int o = 16; o; o >>= 1) q += __shfl_xor_sync(0xffffffffu, q, o);
    float rstd = rsqrtf(q * (1.0f / 128.0f) + LN_EPS);

    float4 g4 = reinterpret_cast<const float4*>(gamma)[l];
    float4 b4 = reinterpret_cast<const float4*>(beta)[l];
    float4 o4;
    o4.x = dx * rstd * g4.x + b4.x; o4.y = dy * rstd * g4.y + b4.y;
    o4.z = dz * rstd * g4.z + b4.z; o4.w = dw * rstd * g4.w + b4.w;
    reinterpret_cast<float4*>(out)[(size_t)gw * 32 + l] = o4;
}

// ---------------- launcher ----------------
extern "C" void kernel_launch(void* const* d_in, const int* in_sizes, int n_in,
                              void* d_out, int out_size) {
    const float* h     = (const float*)d_in[0];
    const void*  eidx  = d_in[1];
    const float* ea    = (const float*)d_in[2];
    const float* W1    = (const float*)d_in[3];
    const float* b1    = (const float*)d_in[4];
    const float* W2    = (const float*)d_in[5];
    const float* b2    = (const float*)d_in[6];
    const float* gamma = (const float*)d_in[7];
    const float* beta  = (const float*)d_in[8];
    float*       out   = (float*)d_out;

    cudaFuncSetAttribute(msg_kernel, cudaFuncAttributeMaxDynamicSharedMemorySize,
                         MSG_SMEM_BYTES);
    cudaFuncSetAttribute(p_kernel, cudaFuncAttributeMaxDynamicSharedMemorySize,
                         P_SMEM_W * 4);

    int sms = 148;
    if (cudaDeviceGetAttribute(&sms, cudaDevAttrMultiProcessorCount, 0) != cudaSuccess
        || sms <= 0) sms = 148;

    detect_zero_kernel<<<(V / 4 + 255) / 256, 256>>>((const int*)eidx);
    hist_zero_kernel<<<(V * D / 4 + 255) / 256, 256>>>(eidx);
    scan1_kernel<<<NB1, 256>>>();
    scan3_kernel<<<NB1, 256>>>();
    permute_kernel<<<(E_TOT + 255) / 256, 256>>>(eidx);
    p_kernel<<<(V + 127) / 128, 256, P_SMEM_W * 4>>>(h, W1, b1);
    msg_kernel<<<2 * sms, 256, MSG_SMEM_BYTES>>>(ea, W1, W2, b2);
    ln_kernel<<<(V * 32 + 255) / 256, 256>>>(h, gamma, beta, out);
}